// round 2
// baseline (speedup 1.0000x reference)
#include <cuda_runtime.h>
#include <cuda_bf16.h>
#include <cstddef>

// Problem constants
#define BATCH   2
#define LSEQ    2048
#define DMODEL  1024
#define NHEADS  16
#define HDIM    64
#define MROWS   (BATCH*LSEQ)      // 4096

#define NEG_INF (__int_as_float(0xff800000))

// Scratch buffers (device globals: no allocations allowed)
__device__ float g_Q[MROWS*DMODEL];
__device__ float g_K[MROWS*DMODEL];
__device__ float g_V[MROWS*DMODEL];
__device__ float g_C[MROWS*DMODEL];

// ---------------------------------------------------------------------------
// SGEMM: C[M,N] = A[M,K] * W[N,K]^T (+ bias[N]).  M,N mult of 128, K mult of 16.
// Block 128x128x16, 256 threads, 8x8 per thread (split 4+4 across halves).
// ---------------------------------------------------------------------------
template<bool BIAS>
__global__ void __launch_bounds__(256)
sgemm_nt(const float* __restrict__ A, const float* __restrict__ W,
         const float* __restrict__ bias, float* __restrict__ C,
         int M, int N, int K)
{
    __shared__ float As[16][128];
    __shared__ float Ws[16][128];

    const int t    = threadIdx.x;
    const int tx   = t & 15;
    const int ty   = t >> 4;
    const int m0   = blockIdx.y * 128;
    const int n0   = blockIdx.x * 128;
    const int lrow = t >> 2;          // 0..63
    const int lk4  = (t & 3) * 4;     // 0,4,8,12

    float acc[8][8];
    #pragma unroll
    for (int i = 0; i < 8; i++)
        #pragma unroll
        for (int j = 0; j < 8; j++) acc[i][j] = 0.f;

    for (int k0 = 0; k0 < K; k0 += 16) {
        float4 a0 = *(const float4*)&A[(size_t)(m0 + lrow)      * K + k0 + lk4];
        float4 a1 = *(const float4*)&A[(size_t)(m0 + lrow + 64) * K + k0 + lk4];
        float4 w0 = *(const float4*)&W[(size_t)(n0 + lrow)      * K + k0 + lk4];
        float4 w1 = *(const float4*)&W[(size_t)(n0 + lrow + 64) * K + k0 + lk4];
        __syncthreads();
        As[lk4+0][lrow]    = a0.x; As[lk4+1][lrow]    = a0.y;
        As[lk4+2][lrow]    = a0.z; As[lk4+3][lrow]    = a0.w;
        As[lk4+0][lrow+64] = a1.x; As[lk4+1][lrow+64] = a1.y;
        As[lk4+2][lrow+64] = a1.z; As[lk4+3][lrow+64] = a1.w;
        Ws[lk4+0][lrow]    = w0.x; Ws[lk4+1][lrow]    = w0.y;
        Ws[lk4+2][lrow]    = w0.z; Ws[lk4+3][lrow]    = w0.w;
        Ws[lk4+0][lrow+64] = w1.x; Ws[lk4+1][lrow+64] = w1.y;
        Ws[lk4+2][lrow+64] = w1.z; Ws[lk4+3][lrow+64] = w1.w;
        __syncthreads();

        #pragma unroll
        for (int k = 0; k < 16; k++) {
            float4 aA = *(float4*)&As[k][ty*4];
            float4 aB = *(float4*)&As[k][ty*4 + 64];
            float4 bA = *(float4*)&Ws[k][tx*4];
            float4 bB = *(float4*)&Ws[k][tx*4 + 64];
            float av[8] = {aA.x,aA.y,aA.z,aA.w, aB.x,aB.y,aB.z,aB.w};
            float bv[8] = {bA.x,bA.y,bA.z,bA.w, bB.x,bB.y,bB.z,bB.w};
            #pragma unroll
            for (int i = 0; i < 8; i++)
                #pragma unroll
                for (int j = 0; j < 8; j++)
                    acc[i][j] += av[i] * bv[j];
        }
    }

    float4 bb0 = make_float4(0.f,0.f,0.f,0.f);
    float4 bb1 = make_float4(0.f,0.f,0.f,0.f);
    if (BIAS) {
        bb0 = *(const float4*)&bias[n0 + tx*4];
        bb1 = *(const float4*)&bias[n0 + tx*4 + 64];
    }
    #pragma unroll
    for (int i = 0; i < 8; i++) {
        int r = m0 + ty*4 + ((i < 4) ? i : i + 60);
        float* cp = &C[(size_t)r * N + n0 + tx*4];
        float4 o0 = make_float4(acc[i][0]+bb0.x, acc[i][1]+bb0.y,
                                acc[i][2]+bb0.z, acc[i][3]+bb0.w);
        float4 o1 = make_float4(acc[i][4]+bb1.x, acc[i][5]+bb1.y,
                                acc[i][6]+bb1.z, acc[i][7]+bb1.w);
        *(float4*)cp        = o0;
        *(float4*)(cp + 64) = o1;
    }
}

// ---------------------------------------------------------------------------
// Flash attention, fp32. Grid (32 q-tiles, 32 b*h). 256 threads = 8 warps.
// Each warp owns 8 query rows. Lane owns cols/dims {lane, lane+32}.
// smem tiles padded to stride 68 floats (bank-conflict-free).
// ---------------------------------------------------------------------------
#define TS 68
#define ATTN_SMEM ((4*64*TS)*4 + 64*4)

__global__ void __launch_bounds__(256)
attn_kernel(const float* __restrict__ Q, const float* __restrict__ K,
            const float* __restrict__ V, const int* __restrict__ mask,
            float* __restrict__ ctx)
{
    extern __shared__ float sm[];
    float* Qs = sm;
    float* Ks = sm + 64*TS;
    float* Vs = sm + 2*64*TS;
    float* Ps = sm + 3*64*TS;
    int*   mk = (int*)(sm + 4*64*TS);

    const int qt   = blockIdx.x;            // 0..31
    const int bh   = blockIdx.y;            // 0..31
    const int b    = bh >> 4;
    const int h    = bh & 15;
    const int tid  = threadIdx.x;
    const int w    = tid >> 5;
    const int lane = tid & 31;

    const float* Qb = Q + ((size_t)b*LSEQ + qt*64) * DMODEL + h*HDIM;
    const float* Kb = K + (size_t)b*LSEQ * DMODEL + h*HDIM;
    const float* Vb = V + (size_t)b*LSEQ * DMODEL + h*HDIM;
    const int*   mb = mask + b*LSEQ;

    // Load Q tile (64x64)
    for (int i = tid; i < 64*16; i += 256) {
        int r = i >> 4, c4 = (i & 15) * 4;
        *(float4*)&Qs[r*TS + c4] = *(const float4*)&Qb[(size_t)r*DMODEL + c4];
    }
    __syncthreads();

    float O0[8], O1[8], mrow[8], lrow[8];
    #pragma unroll
    for (int i = 0; i < 8; i++) { O0[i]=0.f; O1[i]=0.f; lrow[i]=0.f; mrow[i]=NEG_INF; }

    const int c0 = lane, c1 = lane + 32;

    for (int kt = 0; kt < 32; kt++) {
        __syncthreads();
        for (int i = tid; i < 64*16; i += 256) {
            int r = i >> 4, c4 = (i & 15) * 4;
            *(float4*)&Ks[r*TS + c4] = *(const float4*)&Kb[(size_t)(kt*64 + r)*DMODEL + c4];
            *(float4*)&Vs[r*TS + c4] = *(const float4*)&Vb[(size_t)(kt*64 + r)*DMODEL + c4];
        }
        if (tid < 64) mk[tid] = mb[kt*64 + tid];
        __syncthreads();

        // S = Q * K^T for this warp's 8 rows, lane's 2 key columns
        float s0[8], s1[8];
        #pragma unroll
        for (int i = 0; i < 8; i++) { s0[i]=0.f; s1[i]=0.f; }
        #pragma unroll
        for (int d4 = 0; d4 < 16; d4++) {
            float4 k0 = *(float4*)&Ks[c0*TS + d4*4];
            float4 k1 = *(float4*)&Ks[c1*TS + d4*4];
            #pragma unroll
            for (int i = 0; i < 8; i++) {
                float4 q = *(float4*)&Qs[(w*8 + i)*TS + d4*4];
                s0[i] += q.x*k0.x + q.y*k0.y + q.z*k0.z + q.w*k0.w;
                s1[i] += q.x*k1.x + q.y*k1.y + q.z*k1.z + q.w*k1.w;
            }
        }

        const bool keep0 = (mk[c0] != 0);
        const bool keep1 = (mk[c1] != 0);

        // Online softmax update per row
        #pragma unroll
        for (int i = 0; i < 8; i++) {
            float a0 = keep0 ? s0[i]*0.125f : NEG_INF;
            float a1 = keep1 ? s1[i]*0.125f : NEG_INF;
            float rmax = fmaxf(a0, a1);
            #pragma unroll
            for (int off = 16; off; off >>= 1)
                rmax = fmaxf(rmax, __shfl_xor_sync(0xffffffffu, rmax, off));
            float mnew = fmaxf(mrow[i], rmax);
            float corr, p0, p1;
            if (mnew == NEG_INF) {           // everything masked so far
                corr = 1.f; p0 = 0.f; p1 = 0.f;
            } else {
                corr = (mrow[i] == NEG_INF) ? 0.f : __expf(mrow[i] - mnew);
                p0 = keep0 ? __expf(a0 - mnew) : 0.f;
                p1 = keep1 ? __expf(a1 - mnew) : 0.f;
            }
            mrow[i] = mnew;
            float ps = p0 + p1;
            #pragma unroll
            for (int off = 16; off; off >>= 1)
                ps += __shfl_xor_sync(0xffffffffu, ps, off);
            lrow[i] = lrow[i]*corr + ps;
            O0[i] *= corr; O1[i] *= corr;
            Ps[(w*8 + i)*TS + c0] = p0;
            Ps[(w*8 + i)*TS + c1] = p1;
        }
        __syncwarp();

        // O += P * V  (lane's dims d0=lane, d1=lane+32)
        #pragma unroll
        for (int c4 = 0; c4 < 16; c4++) {
            float v0[4], v1[4];
            #pragma unroll
            for (int u = 0; u < 4; u++) {
                v0[u] = Vs[(c4*4 + u)*TS + c0];
                v1[u] = Vs[(c4*4 + u)*TS + c1];
            }
            #pragma unroll
            for (int i = 0; i < 8; i++) {
                float4 p = *(float4*)&Ps[(w*8 + i)*TS + c4*4];
                O0[i] += p.x*v0[0] + p.y*v0[1] + p.z*v0[2] + p.w*v0[3];
                O1[i] += p.x*v1[0] + p.y*v1[1] + p.z*v1[2] + p.w*v1[3];
            }
        }
    }

    // Normalize and write ctx in (B, L, D) layout (heads recombined)
    #pragma unroll
    for (int i = 0; i < 8; i++) {
        int r = w*8 + i;
        float inv = (lrow[i] > 0.f) ? (1.f / lrow[i]) : 0.f;
        float* dst = ctx + ((size_t)b*LSEQ + qt*64 + r) * DMODEL + h*HDIM;
        dst[lane]      = O0[i] * inv;
        dst[lane + 32] = O1[i] * inv;
    }
}

// ---------------------------------------------------------------------------
extern "C" void kernel_launch(void* const* d_in, const int* in_sizes, int n_in,
                              void* d_out, int out_size)
{
    const float* q    = (const float*)d_in[0];
    const float* k    = (const float*)d_in[1];
    const float* v    = (const float*)d_in[2];
    const int*   mask = (const int*)  d_in[3];
    const float* Wq   = (const float*)d_in[4];
    const float* Wk   = (const float*)d_in[5];
    const float* Wv   = (const float*)d_in[6];
    const float* Wo   = (const float*)d_in[7];
    const float* bo   = (const float*)d_in[8];
    float* out = (float*)d_out;

    float *gQ, *gK, *gV, *gC;
    cudaGetSymbolAddress((void**)&gQ, g_Q);
    cudaGetSymbolAddress((void**)&gK, g_K);
    cudaGetSymbolAddress((void**)&gV, g_V);
    cudaGetSymbolAddress((void**)&gC, g_C);

    dim3 gg(DMODEL/128, MROWS/128);   // (8, 32)
    dim3 tt(256);

    sgemm_nt<false><<<gg, tt>>>(q, Wq, nullptr, gQ, MROWS, DMODEL, DMODEL);
    sgemm_nt<false><<<gg, tt>>>(k, Wk, nullptr, gK, MROWS, DMODEL, DMODEL);
    sgemm_nt<false><<<gg, tt>>>(v, Wv, nullptr, gV, MROWS, DMODEL, DMODEL);

    cudaFuncSetAttribute(attn_kernel,
                         cudaFuncAttributeMaxDynamicSharedMemorySize, ATTN_SMEM);
    attn_kernel<<<dim3(LSEQ/64, BATCH*NHEADS), tt, ATTN_SMEM>>>(gQ, gK, gV, mask, gC);

    sgemm_nt<true><<<gg, tt>>>(gC, Wo, bo, out, MROWS, DMODEL, DMODEL);
}

// round 4
// speedup vs baseline: 2.7241x; 2.7241x over previous
#include <cuda_runtime.h>
#include <cuda_bf16.h>
#include <cstdint>
#include <cstddef>

#define BATCH   2
#define LSEQ    2048
#define DMODEL  1024
#define NHEADS  16
#define HDIM    64
#define MROWS   (BATCH*LSEQ)      // 4096

#define NEG_INF (__int_as_float(0xff800000))

// Scratch (device globals: no allocations allowed)
__device__ float g_Q[MROWS*DMODEL];
__device__ float g_K[MROWS*DMODEL];
__device__ float g_V[MROWS*DMODEL];
__device__ float g_C[MROWS*DMODEL];

__device__ __forceinline__ float to_tf32(float x) {
    uint32_t u;
    asm("cvt.rna.tf32.f32 %0, %1;" : "=r"(u) : "f"(x));
    return __uint_as_float(u);
}

__device__ __forceinline__ void mma_tf32(float c[4], const uint32_t a[4],
                                         uint32_t b0, uint32_t b1) {
    asm volatile(
        "mma.sync.aligned.m16n8k8.row.col.f32.tf32.tf32.f32 "
        "{%0,%1,%2,%3}, {%4,%5,%6,%7}, {%8,%9}, {%0,%1,%2,%3};\n"
        : "+f"(c[0]), "+f"(c[1]), "+f"(c[2]), "+f"(c[3])
        : "r"(a[0]), "r"(a[1]), "r"(a[2]), "r"(a[3]), "r"(b0), "r"(b1));
}

// ---------------------------------------------------------------------------
// tf32 GEMM: C[M,N] = A[M,K] * W[N,K]^T (+bias). 128x128 tile, K-tile 32.
// 8 warps as 2x4; warp tile 64x32 (4 m-tiles x 4 n-tiles of m16n8k8).
// ---------------------------------------------------------------------------
template<bool BIAS>
__global__ void __launch_bounds__(256)
gemm_tf32(const float* __restrict__ A, const float* __restrict__ W,
          const float* __restrict__ bias, float* __restrict__ C,
          int M, int N, int K)
{
    __shared__ float As[128][36];
    __shared__ float Ws[128][36];

    const int tid  = threadIdx.x;
    const int w    = tid >> 5;
    const int lane = tid & 31;
    const int g    = lane >> 2;
    const int tig  = lane & 3;
    const int wm   = (w >> 2) * 64;
    const int wn   = (w & 3) * 32;
    const int m0   = blockIdx.y * 128;
    const int n0   = blockIdx.x * 128;

    const int lr = tid >> 1;          // 0..127
    const int lc = (tid & 1) * 16;    // 0 or 16

    float acc[4][4][4];
    #pragma unroll
    for (int mt = 0; mt < 4; mt++)
        #pragma unroll
        for (int nt = 0; nt < 4; nt++)
            #pragma unroll
            for (int u = 0; u < 4; u++) acc[mt][nt][u] = 0.f;

    for (int k0 = 0; k0 < K; k0 += 32) {
        float4 av[4], wv[4];
        #pragma unroll
        for (int u = 0; u < 4; u++) {
            av[u] = *(const float4*)&A[(size_t)(m0 + lr) * K + k0 + lc + u*4];
            wv[u] = *(const float4*)&W[(size_t)(n0 + lr) * K + k0 + lc + u*4];
        }
        __syncthreads();
        #pragma unroll
        for (int u = 0; u < 4; u++) {
            float4 ac = make_float4(to_tf32(av[u].x), to_tf32(av[u].y),
                                    to_tf32(av[u].z), to_tf32(av[u].w));
            float4 wc = make_float4(to_tf32(wv[u].x), to_tf32(wv[u].y),
                                    to_tf32(wv[u].z), to_tf32(wv[u].w));
            *(float4*)&As[lr][lc + u*4] = ac;
            *(float4*)&Ws[lr][lc + u*4] = wc;
        }
        __syncthreads();

        #pragma unroll
        for (int ks = 0; ks < 4; ks++) {
            const int kk = ks * 8;
            uint32_t af[4][4], bf[4][2];
            #pragma unroll
            for (int mt = 0; mt < 4; mt++) {
                af[mt][0] = __float_as_uint(As[wm + mt*16 + g    ][kk + tig]);
                af[mt][1] = __float_as_uint(As[wm + mt*16 + g + 8][kk + tig]);
                af[mt][2] = __float_as_uint(As[wm + mt*16 + g    ][kk + tig + 4]);
                af[mt][3] = __float_as_uint(As[wm + mt*16 + g + 8][kk + tig + 4]);
            }
            #pragma unroll
            for (int nt = 0; nt < 4; nt++) {
                bf[nt][0] = __float_as_uint(Ws[wn + nt*8 + g][kk + tig]);
                bf[nt][1] = __float_as_uint(Ws[wn + nt*8 + g][kk + tig + 4]);
            }
            #pragma unroll
            for (int mt = 0; mt < 4; mt++)
                #pragma unroll
                for (int nt = 0; nt < 4; nt++)
                    mma_tf32(acc[mt][nt], af[mt], bf[nt][0], bf[nt][1]);
        }
    }

    #pragma unroll
    for (int mt = 0; mt < 4; mt++) {
        #pragma unroll
        for (int nt = 0; nt < 4; nt++) {
            int row = m0 + wm + mt*16 + g;
            int col = n0 + wn + nt*8 + 2*tig;
            float b0 = 0.f, b1 = 0.f;
            if (BIAS) { b0 = bias[col]; b1 = bias[col + 1]; }
            *(float2*)&C[(size_t)row * N + col] =
                make_float2(acc[mt][nt][0] + b0, acc[mt][nt][1] + b1);
            *(float2*)&C[(size_t)(row + 8) * N + col] =
                make_float2(acc[mt][nt][2] + b0, acc[mt][nt][3] + b1);
        }
    }
}

// ---------------------------------------------------------------------------
// Flash attention, tf32 MMA. CTA: 128 q-rows x one (b,h). 8 warps x 16 rows.
// Q fragments hoisted to regs; P staged via smem (aliases Q tile region);
// V transposed to dim-major so it is the col-major B operand directly.
// ---------------------------------------------------------------------------
#define AST 68
#define ATTN_SMEM ((256*AST + 64) * 4)

__global__ void __launch_bounds__(256, 2)
attn_tf32(const float* __restrict__ Q, const float* __restrict__ K,
          const float* __restrict__ V, const int* __restrict__ mask,
          float* __restrict__ ctx)
{
    extern __shared__ float sm[];
    float* Qs  = sm;                 // 128 x AST (aliased as Ps after frag build)
    float* Ks  = sm + 128*AST;       // 64 x AST   [key][dim]
    float* Vt  = Ks + 64*AST;        // 64 x AST   [dim][key]
    float* Ps  = Qs;
    float* mkf = Vt + 64*AST;        // 64 additive mask (0 / -inf)

    const int qt   = blockIdx.x;     // 0..15
    const int bh   = blockIdx.y;     // 0..31
    const int b    = bh >> 4;
    const int h    = bh & 15;
    const int tid  = threadIdx.x;
    const int w    = tid >> 5;
    const int lane = tid & 31;
    const int g    = lane >> 2;
    const int tig  = lane & 3;
    const int qb   = w * 16;

    const float* Qb = Q + ((size_t)b*LSEQ + qt*128) * DMODEL + h*HDIM;
    const float* Kb = K + (size_t)b*LSEQ * DMODEL + h*HDIM;
    const float* Vb = V + (size_t)b*LSEQ * DMODEL + h*HDIM;
    const int*   mb = mask + b*LSEQ;

    // Load Q tile (128x64), tf32-converted
    for (int i = tid; i < 128*16; i += 256) {
        int r = i >> 4, c4 = (i & 15) * 4;
        float4 qv = *(const float4*)&Qb[(size_t)r*DMODEL + c4];
        *(float4*)&Qs[r*AST + c4] = make_float4(to_tf32(qv.x), to_tf32(qv.y),
                                                to_tf32(qv.z), to_tf32(qv.w));
    }
    __syncthreads();

    // Hoist Q fragments (loop-invariant across key tiles)
    uint32_t aQ[8][4];
    #pragma unroll
    for (int ks = 0; ks < 8; ks++) {
        const int kk = ks * 8;
        aQ[ks][0] = __float_as_uint(Qs[(qb + g    )*AST + kk + tig]);
        aQ[ks][1] = __float_as_uint(Qs[(qb + g + 8)*AST + kk + tig]);
        aQ[ks][2] = __float_as_uint(Qs[(qb + g    )*AST + kk + tig + 4]);
        aQ[ks][3] = __float_as_uint(Qs[(qb + g + 8)*AST + kk + tig + 4]);
    }
    __syncthreads();   // Qs now reusable as Ps

    float o[8][4];
    #pragma unroll
    for (int j = 0; j < 8; j++)
        #pragma unroll
        for (int u = 0; u < 4; u++) o[j][u] = 0.f;
    float m0r = NEG_INF, m1r = NEG_INF, l0 = 0.f, l1 = 0.f;

    for (int kt = 0; kt < 32; kt++) {
        __syncthreads();
        for (int i = tid; i < 64*16; i += 256) {
            int r = i >> 4, c4 = (i & 15) * 4;
            float4 kv = *(const float4*)&Kb[(size_t)(kt*64 + r)*DMODEL + c4];
            float4 vv = *(const float4*)&Vb[(size_t)(kt*64 + r)*DMODEL + c4];
            *(float4*)&Ks[r*AST + c4] = make_float4(to_tf32(kv.x), to_tf32(kv.y),
                                                    to_tf32(kv.z), to_tf32(kv.w));
            Vt[(c4+0)*AST + r] = to_tf32(vv.x);
            Vt[(c4+1)*AST + r] = to_tf32(vv.y);
            Vt[(c4+2)*AST + r] = to_tf32(vv.z);
            Vt[(c4+3)*AST + r] = to_tf32(vv.w);
        }
        if (tid < 64) mkf[tid] = (mb[kt*64 + tid] != 0) ? 0.f : NEG_INF;
        __syncthreads();

        // S = Q K^T  (16 rows x 64 keys per warp)
        float s[8][4];
        #pragma unroll
        for (int j = 0; j < 8; j++)
            #pragma unroll
            for (int u = 0; u < 4; u++) s[j][u] = 0.f;
        #pragma unroll
        for (int ks = 0; ks < 8; ks++) {
            const int kk = ks * 8;
            #pragma unroll
            for (int j = 0; j < 8; j++) {
                uint32_t b0 = __float_as_uint(Ks[(j*8 + g)*AST + kk + tig]);
                uint32_t b1 = __float_as_uint(Ks[(j*8 + g)*AST + kk + tig + 4]);
                mma_tf32(s[j], aQ[ks], b0, b1);
            }
        }

        // scale + additive mask; row maxes
        float rm0 = NEG_INF, rm1 = NEG_INF;
        #pragma unroll
        for (int j = 0; j < 8; j++) {
            float ma = mkf[j*8 + 2*tig];
            float mbv = mkf[j*8 + 2*tig + 1];
            s[j][0] = s[j][0]*0.125f + ma;
            s[j][1] = s[j][1]*0.125f + mbv;
            s[j][2] = s[j][2]*0.125f + ma;
            s[j][3] = s[j][3]*0.125f + mbv;
            rm0 = fmaxf(rm0, fmaxf(s[j][0], s[j][1]));
            rm1 = fmaxf(rm1, fmaxf(s[j][2], s[j][3]));
        }
        rm0 = fmaxf(rm0, __shfl_xor_sync(0xffffffffu, rm0, 1));
        rm0 = fmaxf(rm0, __shfl_xor_sync(0xffffffffu, rm0, 2));
        rm1 = fmaxf(rm1, __shfl_xor_sync(0xffffffffu, rm1, 1));
        rm1 = fmaxf(rm1, __shfl_xor_sync(0xffffffffu, rm1, 2));

        float mn0 = fmaxf(m0r, rm0), mn1 = fmaxf(m1r, rm1);
        float corr0 = (mn0 == NEG_INF) ? 1.f : __expf(m0r - mn0);
        float corr1 = (mn1 == NEG_INF) ? 1.f : __expf(m1r - mn1);
        float ps0 = 0.f, ps1 = 0.f;
        #pragma unroll
        for (int j = 0; j < 8; j++) {
            float p00 = (mn0 == NEG_INF) ? 0.f : __expf(s[j][0] - mn0);
            float p01 = (mn0 == NEG_INF) ? 0.f : __expf(s[j][1] - mn0);
            float p10 = (mn1 == NEG_INF) ? 0.f : __expf(s[j][2] - mn1);
            float p11 = (mn1 == NEG_INF) ? 0.f : __expf(s[j][3] - mn1);
            ps0 += p00 + p01;
            ps1 += p10 + p11;
            Ps[(qb + g    )*AST + j*8 + 2*tig    ] = to_tf32(p00);
            Ps[(qb + g    )*AST + j*8 + 2*tig + 1] = to_tf32(p01);
            Ps[(qb + g + 8)*AST + j*8 + 2*tig    ] = to_tf32(p10);
            Ps[(qb + g + 8)*AST + j*8 + 2*tig + 1] = to_tf32(p11);
        }
        ps0 += __shfl_xor_sync(0xffffffffu, ps0, 1);
        ps0 += __shfl_xor_sync(0xffffffffu, ps0, 2);
        ps1 += __shfl_xor_sync(0xffffffffu, ps1, 1);
        ps1 += __shfl_xor_sync(0xffffffffu, ps1, 2);
        l0 = l0*corr0 + ps0;
        l1 = l1*corr1 + ps1;
        m0r = mn0; m1r = mn1;
        #pragma unroll
        for (int j = 0; j < 8; j++) {
            o[j][0] *= corr0; o[j][1] *= corr0;
            o[j][2] *= corr1; o[j][3] *= corr1;
        }
        __syncwarp();

        // O += P V
        #pragma unroll
        for (int ks = 0; ks < 8; ks++) {
            const int kk = ks * 8;
            uint32_t ap[4];
            ap[0] = __float_as_uint(Ps[(qb + g    )*AST + kk + tig]);
            ap[1] = __float_as_uint(Ps[(qb + g + 8)*AST + kk + tig]);
            ap[2] = __float_as_uint(Ps[(qb + g    )*AST + kk + tig + 4]);
            ap[3] = __float_as_uint(Ps[(qb + g + 8)*AST + kk + tig + 4]);
            #pragma unroll
            for (int j = 0; j < 8; j++) {
                uint32_t b0 = __float_as_uint(Vt[(j*8 + g)*AST + kk + tig]);
                uint32_t b1 = __float_as_uint(Vt[(j*8 + g)*AST + kk + tig + 4]);
                mma_tf32(o[j], ap, b0, b1);
            }
        }
        __syncwarp();
    }

    // Normalize, write ctx (B, L, D)
    float inv0 = (l0 > 0.f) ? (1.f / l0) : 0.f;
    float inv1 = (l1 > 0.f) ? (1.f / l1) : 0.f;
    int r0 = qt*128 + qb + g;
    float* base0 = ctx + ((size_t)b*LSEQ + r0    ) * DMODEL + h*HDIM;
    float* base1 = ctx + ((size_t)b*LSEQ + r0 + 8) * DMODEL + h*HDIM;
    #pragma unroll
    for (int j = 0; j < 8; j++) {
        int col = j*8 + 2*tig;
        *(float2*)&base0[col] = make_float2(o[j][0]*inv0, o[j][1]*inv0);
        *(float2*)&base1[col] = make_float2(o[j][2]*inv1, o[j][3]*inv1);
    }
}

// ---------------------------------------------------------------------------
extern "C" void kernel_launch(void* const* d_in, const int* in_sizes, int n_in,
                              void* d_out, int out_size)
{
    const float* q    = (const float*)d_in[0];
    const float* k    = (const float*)d_in[1];
    const float* v    = (const float*)d_in[2];
    const int*   mask = (const int*)  d_in[3];
    const float* Wq   = (const float*)d_in[4];
    const float* Wk   = (const float*)d_in[5];
    const float* Wv   = (const float*)d_in[6];
    const float* Wo   = (const float*)d_in[7];
    const float* bo   = (const float*)d_in[8];
    float* out = (float*)d_out;

    float *gQ, *gK, *gV, *gC;
    cudaGetSymbolAddress((void**)&gQ, g_Q);
    cudaGetSymbolAddress((void**)&gK, g_K);
    cudaGetSymbolAddress((void**)&gV, g_V);
    cudaGetSymbolAddress((void**)&gC, g_C);

    dim3 gg(DMODEL/128, MROWS/128);   // (8, 32)
    dim3 tt(256);

    gemm_tf32<false><<<gg, tt>>>(q, Wq, nullptr, gQ, MROWS, DMODEL, DMODEL);
    gemm_tf32<false><<<gg, tt>>>(k, Wk, nullptr, gK, MROWS, DMODEL, DMODEL);
    gemm_tf32<false><<<gg, tt>>>(v, Wv, nullptr, gV, MROWS, DMODEL, DMODEL);

    cudaFuncSetAttribute(attn_tf32,
                         cudaFuncAttributeMaxDynamicSharedMemorySize, ATTN_SMEM);
    attn_tf32<<<dim3(LSEQ/128, BATCH*NHEADS), tt, ATTN_SMEM>>>(gQ, gK, gV, mask, gC);

    gemm_tf32<true><<<gg, tt>>>(gC, Wo, bo, out, MROWS, DMODEL, DMODEL);
}